// round 1
// baseline (speedup 1.0000x reference)
#include <cuda_runtime.h>

#define D      128
#define H0     64
#define W0     96
#define NPIX0  (H0*W0)        // 6144
#define NPIX_T 8160           // 6144+1536+384+96

__device__ float g_f1[NPIX_T * D];
__device__ float g_f2[NPIX_T * D];
__device__ float g_crd[NPIX_T * 2];

// ---------------------------------------------------------------------------
// Transpose (D, H*W) -> (H*W, D) for both feature maps (level 0, channel-last)
// ---------------------------------------------------------------------------
__global__ void k_transpose(const float* __restrict__ f1, const float* __restrict__ f2) {
    __shared__ float tile[32][33];
    const float* src = blockIdx.z ? f2 : f1;
    float*       dst = blockIdx.z ? g_f2 : g_f1;
    int p0 = blockIdx.x * 32;   // pixel tile
    int d0 = blockIdx.y * 32;   // channel tile
    #pragma unroll
    for (int i = 0; i < 4; i++)
        tile[threadIdx.y + 8*i][threadIdx.x] =
            src[(d0 + threadIdx.y + 8*i) * NPIX0 + p0 + threadIdx.x];
    __syncthreads();
    #pragma unroll
    for (int i = 0; i < 4; i++)
        dst[(p0 + threadIdx.y + 8*i) * D + d0 + threadIdx.x] =
            tile[threadIdx.x][threadIdx.y + 8*i];
}

// ---------------------------------------------------------------------------
// 2x2 avg pool, channel-last, both maps in one launch
// ---------------------------------------------------------------------------
__global__ void k_pool(int Hl, int Wl, int srcoff, int dstoff) {
    int n   = Hl * Wl * D;
    int idx = blockIdx.x * blockDim.x + threadIdx.x;
    if (idx >= 2 * n) return;
    int m = (idx >= n);
    int q = idx - m * n;
    const float* src = (m ? g_f2 : g_f1) + (size_t)srcoff * D;
    float*       dst = (m ? g_f2 : g_f1) + (size_t)dstoff * D;
    int d  = q & (D - 1);
    int pw = q >> 7;
    int w  = pw % Wl;
    int h  = pw / Wl;
    int Wp = Wl * 2;
    int b  = ((2*h) * Wp + 2*w) * D + d;
    float v = src[b] + src[b + D] + src[b + Wp*D] + src[b + Wp*D + D];
    dst[q] = 0.25f * v;
}

// ---------------------------------------------------------------------------
// Per-level coords: level 0 copy, levels 1-3 = jax.image.resize linear
// (antialias triangle kernel, support 2*s, edge-truncated + renormalized),
// then divided by 2^level.
// ---------------------------------------------------------------------------
__global__ void k_coords(const float* __restrict__ crd) {
    int p = blockIdx.x * blockDim.x + threadIdx.x;
    if (p >= NPIX_T) return;
    int l;
    if      (p >= 8064) l = 3;
    else if (p >= 7680) l = 2;
    else if (p >= 6144) l = 1;
    else                l = 0;
    const int pixoff[4] = {0, 6144, 7680, 8064};
    const int hl[4]     = {64, 32, 16, 8};
    const int wl[4]     = {96, 48, 24, 12};
    int q  = p - pixoff[l];
    int Wl = wl[l];
    int h  = q / Wl, w = q % Wl;
    float gx, gy;
    if (l == 0) {
        gx = crd[q];
        gy = crd[NPIX0 + q];
    } else {
        float s  = (float)(1 << l);
        float cy = (h + 0.5f) * s - 0.5f;
        float cx = (w + 0.5f) * s - 0.5f;
        int jy0 = max(0,     (int)ceilf (cy - s));
        int jy1 = min(H0-1,  (int)floorf(cy + s));
        int jx0 = max(0,     (int)ceilf (cx - s));
        int jx1 = min(W0-1,  (int)floorf(cx + s));
        float sumy = 0.f, sumx = 0.f;
        for (int j = jy0; j <= jy1; j++) sumy += 1.f - fabsf(j - cy) / s;
        for (int i = jx0; i <= jx1; i++) sumx += 1.f - fabsf(i - cx) / s;
        float ax = 0.f, ay = 0.f;
        for (int j = jy0; j <= jy1; j++) {
            float wy = 1.f - fabsf(j - cy) / s;
            for (int i = jx0; i <= jx1; i++) {
                float wgt = wy * (1.f - fabsf(i - cx) / s);
                ax += wgt * crd[j * W0 + i];
                ay += wgt * crd[NPIX0 + j * W0 + i];
            }
        }
        float inv = 1.f / (sumx * sumy * s);
        gx = ax * inv;
        gy = ay * inv;
    }
    g_crd[p*2]   = gx;
    g_crd[p*2+1] = gy;
}

// ---------------------------------------------------------------------------
// Local correlation: one block per pixel.
// Phase 1: 100 window dot-products (warp per dot, float4 lanes, shfl reduce).
// Phase 2: 81 bilinear combines with border clamping (grid_sample border,
//          align_corners=True semantics).
// ---------------------------------------------------------------------------
__global__ void __launch_bounds__(256) k_corr(float* __restrict__ out,
                                              int Hl, int Wl, int pixoff, int outoff) {
    int pix = blockIdx.x;
    int tid = threadIdx.x;
    __shared__ __align__(16) float f1s[D];
    __shared__ float gsh[100];
    __shared__ float sc[2];
    if (tid < D) f1s[tid] = g_f1[(size_t)(pixoff + pix) * D + tid];
    if (tid == 0) {
        sc[0] = g_crd[(pixoff + pix) * 2];
        sc[1] = g_crd[(pixoff + pix) * 2 + 1];
    }
    __syncthreads();
    float cx = sc[0], cy = sc[1];
    int bx = (int)floorf(cx);
    int by = (int)floorf(cy);
    int lane = tid & 31, warp = tid >> 5;
    float4 a = ((const float4*)f1s)[lane];
    const float* f2l = g_f2 + (size_t)pixoff * D;
    for (int pos = warp; pos < 100; pos += 8) {
        int u = pos / 10;
        int t = pos - u * 10;
        int px = min(max(bx + t - 4, 0), Wl - 1);
        int py = min(max(by + u - 4, 0), Hl - 1);
        const float4* f2v = (const float4*)(f2l + (size_t)(py * Wl + px) * D);
        float4 b4 = f2v[lane];
        float sdot = a.x*b4.x + a.y*b4.y + a.z*b4.z + a.w*b4.w;
        #pragma unroll
        for (int o = 16; o > 0; o >>= 1)
            sdot += __shfl_xor_sync(0xffffffffu, sdot, o);
        if (lane == 0) gsh[pos] = sdot;
    }
    __syncthreads();
    if (tid < 81) {
        int adx = tid / 9;          // x-offset index (slow, matches dx)
        int bdy = tid - adx * 9;    // y-offset index (fast, matches dy)
        float fx = cx - floorf(cx);
        float fy = cy - floorf(cy);
        int t0 = bx + adx - 4;
        int u0 = by + bdy - 4;
        float wx1 = (t0 < 0 || t0 >= Wl - 1) ? 0.f : fx;  // clamped -> frac 0
        float wy1 = (u0 < 0 || u0 >= Hl - 1) ? 0.f : fy;
        float wx0 = 1.f - wx1, wy0 = 1.f - wy1;
        float g00 = gsh[bdy * 10 + adx];
        float g01 = gsh[bdy * 10 + adx + 1];
        float g10 = gsh[bdy * 10 + adx + 10];
        float g11 = gsh[bdy * 10 + adx + 11];
        float c = wy0 * (wx0 * g00 + wx1 * g01) + wy1 * (wx0 * g10 + wx1 * g11);
        out[outoff + tid * (Hl * Wl) + pix] = c * 0.08838834764831845f; // 1/sqrt(128)
    }
}

// ---------------------------------------------------------------------------
extern "C" void kernel_launch(void* const* d_in, const int* in_sizes, int n_in,
                              void* d_out, int out_size) {
    const float* f1  = (const float*)d_in[0];
    const float* f2  = (const float*)d_in[1];
    const float* crd = (const float*)d_in[2];
    float* out = (float*)d_out;

    const int HLs[4] = {64, 32, 16, 8};
    const int WLs[4] = {96, 48, 24, 12};
    const int PO[4]  = {0, 6144, 7680, 8064};
    const int OO[4]  = {0, 81*6144, 81*7680, 81*8064};

    dim3 tb(32, 8);
    k_transpose<<<dim3(NPIX0/32, D/32, 2), tb>>>(f1, f2);

    for (int l = 1; l < 4; l++) {
        int n2 = 2 * HLs[l] * WLs[l] * D;
        k_pool<<<(n2 + 255) / 256, 256>>>(HLs[l], WLs[l], PO[l-1], PO[l]);
    }

    k_coords<<<(NPIX_T + 255) / 256, 256>>>(crd);

    for (int l = 0; l < 4; l++)
        k_corr<<<HLs[l] * WLs[l], 256>>>(out, HLs[l], WLs[l], PO[l], OO[l]);
}